// round 9
// baseline (speedup 1.0000x reference)
#include <cuda_runtime.h>
#include <math.h>

#define N_CRIT   128
#define N_PAIRS  8128          // 128*127/2
#define N_TOT    8256          // N_CRIT + N_PAIRS
#define N_VEC4   2064          // N_TOT / 4
#define N_HALF4  1032          // half-row in float4 (1032*16 = 16512 B, 128-aligned)
#define BATCH    16384
#define MIN_W    1e-7f
#define THREADS  512
#define GRID     608           // 152 SMs x 4 resident blocks: one wave
#define MAX_ROWS 27            // ceil(16384 / 608) local rows per block

__device__ float g_w[N_TOT];   // constrained weights (wc_eff ‖ wint_eff)

// ---------------------------------------------------------------------------
// Prep: one pair per thread. grid = 32 x 256 (8192 >= 8128).
// ---------------------------------------------------------------------------
__global__ __launch_bounds__(256)
void prep_weights_kernel(const float* __restrict__ wc,
                         const float* __restrict__ wint) {
    __shared__ float s_wc[N_CRIT];

    const int tid = threadIdx.x;
    if (tid < N_CRIT) {
        float w = wc[tid];
        w = (w < 0.0f) ? MIN_W : w;
        s_wc[tid] = w;
        if (blockIdx.x == 0) g_w[tid] = w;
    }
    __syncthreads();

    const int p = blockIdx.x * 256 + tid;
    if (p < N_PAIRS) {
        // invert start(i) = i*(255-i)/2 via sqrt + integer fixup
        float fi = (255.0f - sqrtf(65025.0f - 8.0f * (float)p)) * 0.5f;
        int i = (int)fi;
        if (i > 126) i = 126;
        if (i < 0) i = 0;
        while (i * (255 - i) / 2 > p) --i;
        while ((i + 1) * (254 - i) / 2 <= p) ++i;
        int j = p - i * (255 - i) / 2 + i + 1;

        g_w[N_CRIT + p] = fmaxf(wint[p], fmaxf(-s_wc[i], -s_wc[j]));
    }
}

// ---------------------------------------------------------------------------
// Persistent GEMV: 608 blocks x 512 threads (16 warps = 8 warp-pairs).
// Pair p handles local rows p, p+8, p+16, ... ; global row = blockIdx + r*608.
// Each warp streams an ALIGNED half-row (1032 float4): 32 unrolled iterations
// per row before a single warp reduce. One block barrier at the very end.
// ---------------------------------------------------------------------------
__global__ __launch_bounds__(THREADS, 4)
void choquet_gemv_kernel(const float* __restrict__ x,
                         const float* __restrict__ thr,
                         float* __restrict__ out) {
    __shared__ __align__(16) float s_w[N_TOT];       // 33 KB
    __shared__ float s_part[MAX_ROWS][2];            // per-(local row, half)
    __shared__ float s_red[THREADS];
    __shared__ float s_inv;

    const int tid = threadIdx.x;

    // stage weights once (coalesced float4) + weight sum
    const float4* gw4 = reinterpret_cast<const float4*>(g_w);
    float4* sw4 = reinterpret_cast<float4*>(s_w);
    float wsum = 0.0f;
    #pragma unroll
    for (int k = tid; k < N_VEC4; k += THREADS) {
        float4 v = gw4[k];
        sw4[k] = v;
        wsum += v.x + v.y + v.z + v.w;
    }
    s_red[tid] = wsum;
    __syncthreads();
    #pragma unroll
    for (int off = THREADS / 2; off > 0; off >>= 1) {
        if (tid < off) s_red[tid] += s_red[tid + off];
        __syncthreads();
    }
    if (tid == 0) s_inv = 1.0f / s_red[0];
    __syncthreads();

    const int warp = tid >> 5;
    const int lane = tid & 31;
    const int pair = warp >> 1;               // 0..7
    const int half = warp & 1;                // 0 or 1
    const int kbase = half * N_HALF4 + lane;  // aligned half-row start

    const size_t row_stride4 = N_VEC4;        // 2064 float4 per row

    // pair p covers local rows p, p+8, p+16, ...
    for (int r = pair; blockIdx.x + r * GRID < BATCH; r += 8) {
        const int row = blockIdx.x + r * GRID;
        const float4* xr = reinterpret_cast<const float4*>(x) +
                           (size_t)row * row_stride4;

        float acc = 0.0f;
        int k = kbase;
        // 1032 float4 / 32 lanes = 32 full iterations + 8-lane tail
        #pragma unroll 4
        for (int it = 0; it < 32; ++it, k += 32) {
            float4 a = __ldcs(&xr[k]);        // streaming: read-once
            float4 b = sw4[k];
            acc = fmaf(a.x, b.x, acc);
            acc = fmaf(a.y, b.y, acc);
            acc = fmaf(a.z, b.z, acc);
            acc = fmaf(a.w, b.w, acc);
        }
        if (lane < 8) {                       // k = half*1032 + 1024 + lane
            float4 a = __ldcs(&xr[k]);
            float4 b = sw4[k];
            acc = fmaf(a.x, b.x, acc);
            acc = fmaf(a.y, b.y, acc);
            acc = fmaf(a.z, b.z, acc);
            acc = fmaf(a.w, b.w, acc);
        }

        // warp reduce
        #pragma unroll
        for (int off = 16; off > 0; off >>= 1) {
            acc += __shfl_xor_sync(0xFFFFFFFFu, acc, off);
        }
        if (lane == 0) s_part[r][half] = acc;
    }

    __syncthreads();   // all pairs done with all their rows

    // thread r combines the two half-row partials of local row r
    if (tid < MAX_ROWS) {
        const int row = blockIdx.x + tid * GRID;
        if (row < BATCH) {
            float dot = s_part[tid][0] + s_part[tid][1];
            float score = dot * s_inv - thr[0];
            out[row] = 1.0f / (1.0f + expf(-score));
        }
    }
}

// ---------------------------------------------------------------------------
extern "C" void kernel_launch(void* const* d_in, const int* in_sizes, int n_in,
                              void* d_out, int out_size) {
    const float* x    = (const float*)d_in[0];
    const float* wc   = (const float*)d_in[1];
    const float* wint = (const float*)d_in[2];
    const float* thr  = (const float*)d_in[3];
    float* out = (float*)d_out;

    prep_weights_kernel<<<32, 256>>>(wc, wint);
    choquet_gemv_kernel<<<GRID, THREADS>>>(x, thr, out);
}